// round 1
// baseline (speedup 1.0000x reference)
#include <cuda_runtime.h>

// Problem constants (hardcoded; H=W=56 inputs ignored)
#define B_    32
#define NTOK  3136
#define C_    384
#define NH    12
#define D_    32

// ---------------- scratch (device globals; no allocation allowed) -------------
__device__ float g_Q[(size_t)B_ * NH * NTOK * D_];   // [b*12+h][n][d]
__device__ float g_K[(size_t)B_ * NH * NTOK * D_];
__device__ float g_V[(size_t)B_ * NH * NTOK * D_];
__device__ float g_Q1[B_ * 4 * 784 * D_];            // scale 1 (28x28), heads 4..7
__device__ float g_K1[B_ * 4 * 784 * D_];
__device__ float g_V1[B_ * 4 * 784 * D_];
__device__ float g_Q2[B_ * 4 * 196 * D_];            // scale 2 (14x14), heads 8..11
__device__ float g_K2[B_ * 4 * 196 * D_];
__device__ float g_V2[B_ * 4 * 196 * D_];
__device__ float g_Z[(size_t)B_ * NTOK * C_];        // attention output, patch-order rows

// ---------------- SGEMM 1: qkv = x @ [Wq | Wkv], scatter epilogue --------------
// M = 100352 (784 blocks of 128), N = 1152 (9 blocks), K = 384. All exact multiples.
__global__ __launch_bounds__(256, 2)
void gemm_qkv(const float* __restrict__ X,
              const float* __restrict__ Wq,
              const float* __restrict__ Wkv)
{
    __shared__ float As[8][128];
    __shared__ float Bs[8][128];

    const int tid = threadIdx.x;
    const int tx = tid & 15, ty = tid >> 4;
    const int rowBase = blockIdx.y * 128;
    const int colBase = blockIdx.x * 128;

    const float* Wp; int ldw, colW;
    if (colBase < 384) { Wp = Wq;  ldw = 384; colW = colBase; }
    else               { Wp = Wkv; ldw = 768; colW = colBase - 384; }

    const int ar = tid >> 1, ak = (tid & 1) << 2;   // A: 128 rows x 8 k
    const int bk = tid >> 5, bc = (tid & 31) << 2;  // B: 8 k x 128 cols

    float acc[8][8];
#pragma unroll
    for (int i = 0; i < 8; i++)
#pragma unroll
        for (int j = 0; j < 8; j++) acc[i][j] = 0.f;

    for (int k0 = 0; k0 < 384; k0 += 8) {
        float4 av = *(const float4*)(X + (size_t)(rowBase + ar) * 384 + k0 + ak);
        float4 bv = *(const float4*)(Wp + (size_t)(k0 + bk) * ldw + colW + bc);
        As[ak + 0][ar] = av.x; As[ak + 1][ar] = av.y;
        As[ak + 2][ar] = av.z; As[ak + 3][ar] = av.w;
        *(float4*)&Bs[bk][bc] = bv;
        __syncthreads();
#pragma unroll
        for (int kk = 0; kk < 8; kk++) {
            float4 a0 = *(const float4*)&As[kk][ty * 8];
            float4 a1 = *(const float4*)&As[kk][ty * 8 + 4];
            float4 b0 = *(const float4*)&Bs[kk][tx * 8];
            float4 b1 = *(const float4*)&Bs[kk][tx * 8 + 4];
            float a[8] = {a0.x, a0.y, a0.z, a0.w, a1.x, a1.y, a1.z, a1.w};
            float b[8] = {b0.x, b0.y, b0.z, b0.w, b1.x, b1.y, b1.z, b1.w};
#pragma unroll
            for (int i = 0; i < 8; i++)
#pragma unroll
                for (int j = 0; j < 8; j++)
                    acc[i][j] = fmaf(a[i], b[j], acc[i][j]);
        }
        __syncthreads();
    }

    // Scatter epilogue into Q/K/V layout [b*12+h][n][d]
#pragma unroll
    for (int i = 0; i < 8; i++) {
        int m = rowBase + ty * 8 + i;
        int b = m / NTOK, n = m % NTOK;
#pragma unroll
        for (int j = 0; j < 8; j++) {
            int cg = colBase + tx * 8 + j;
            float v = acc[i][j];
            if (cg < 384) {
                int h = cg >> 5, dd = cg & 31;
                g_Q[((size_t)(b * 12 + h) * NTOK + n) * 32 + dd] = v;
            } else {
                int j2 = cg - 384;                 // [0,768): kk*384 + h*32 + dd
                int h = (j2 >> 5) % 12;
                int dd = j2 & 31;
                float* dst = (j2 >= 384) ? g_V : g_K;
                dst[((size_t)(b * 12 + h) * NTOK + n) * 32 + dd] = v;
            }
        }
    }
}

// ---------------- SGEMM 2: out = Z @ Wproj + bproj ----------------------------
__global__ __launch_bounds__(256, 2)
void gemm_proj(const float* __restrict__ Wproj,
               const float* __restrict__ bproj,
               float* __restrict__ out)
{
    __shared__ float As[8][128];
    __shared__ float Bs[8][128];

    const int tid = threadIdx.x;
    const int tx = tid & 15, ty = tid >> 4;
    const int rowBase = blockIdx.y * 128;
    const int colBase = blockIdx.x * 128;

    const int ar = tid >> 1, ak = (tid & 1) << 2;
    const int bk = tid >> 5, bc = (tid & 31) << 2;

    float acc[8][8];
#pragma unroll
    for (int i = 0; i < 8; i++)
#pragma unroll
        for (int j = 0; j < 8; j++) acc[i][j] = 0.f;

    for (int k0 = 0; k0 < 384; k0 += 8) {
        float4 av = *(const float4*)(g_Z + (size_t)(rowBase + ar) * 384 + k0 + ak);
        float4 bv = *(const float4*)(Wproj + (size_t)(k0 + bk) * 384 + colBase + bc);
        As[ak + 0][ar] = av.x; As[ak + 1][ar] = av.y;
        As[ak + 2][ar] = av.z; As[ak + 3][ar] = av.w;
        *(float4*)&Bs[bk][bc] = bv;
        __syncthreads();
#pragma unroll
        for (int kk = 0; kk < 8; kk++) {
            float4 a0 = *(const float4*)&As[kk][ty * 8];
            float4 a1 = *(const float4*)&As[kk][ty * 8 + 4];
            float4 b0 = *(const float4*)&Bs[kk][tx * 8];
            float4 b1 = *(const float4*)&Bs[kk][tx * 8 + 4];
            float a[8] = {a0.x, a0.y, a0.z, a0.w, a1.x, a1.y, a1.z, a1.w};
            float b[8] = {b0.x, b0.y, b0.z, b0.w, b1.x, b1.y, b1.z, b1.w};
#pragma unroll
            for (int i = 0; i < 8; i++)
#pragma unroll
                for (int j = 0; j < 8; j++)
                    acc[i][j] = fmaf(a[i], b[j], acc[i][j]);
        }
        __syncthreads();
    }

#pragma unroll
    for (int i = 0; i < 8; i++) {
        int m = rowBase + ty * 8 + i;
#pragma unroll
        for (int j = 0; j < 8; j++) {
            int cg = colBase + tx * 8 + j;
            out[(size_t)m * 384 + cg] = acc[i][j] + bproj[cg];
        }
    }
}

// ---------------- depthwise convs (downsample heads 4-7 and 8-11) -------------
// conv1: 2x2, stride 2, pad 0 -> 28x28
__global__ void dwconv1(const float* __restrict__ w, const float* __restrict__ bias)
{
    int which = blockIdx.y;
    const float* src = which == 0 ? g_Q : which == 1 ? g_K : g_V;
    float* dst       = which == 0 ? g_Q1 : which == 1 ? g_K1 : g_V1;
    int bg = blockIdx.x;                 // 0..127
    int b = bg >> 2, hl = bg & 3;
    const float* s = src + ((size_t)(b * 12 + 4 + hl)) * NTOK * 32;
    float* d = dst + (size_t)bg * 784 * 32;
    for (int idx = threadIdx.x; idx < 784 * 32; idx += blockDim.x) {
        int c = idx & 31;
        int xy = idx >> 5;
        int xo = xy % 28, yo = xy / 28;
        float acc = bias[c];
#pragma unroll
        for (int i = 0; i < 2; i++)
#pragma unroll
            for (int j = 0; j < 2; j++)
                acc = fmaf(s[((2 * yo + i) * 56 + 2 * xo + j) * 32 + c],
                           w[(i * 2 + j) * 32 + c], acc);
        d[idx] = acc;
    }
}

// conv2: 2x2, stride 4, pad 1, dilation 2 -> 14x14 (taps at 4y-1, 4y+1)
__global__ void dwconv2(const float* __restrict__ w, const float* __restrict__ bias)
{
    int which = blockIdx.y;
    const float* src = which == 0 ? g_Q : which == 1 ? g_K : g_V;
    float* dst       = which == 0 ? g_Q2 : which == 1 ? g_K2 : g_V2;
    int bg = blockIdx.x;
    int b = bg >> 2, hl = bg & 3;
    const float* s = src + ((size_t)(b * 12 + 8 + hl)) * NTOK * 32;
    float* d = dst + (size_t)bg * 196 * 32;
    for (int idx = threadIdx.x; idx < 196 * 32; idx += blockDim.x) {
        int c = idx & 31;
        int xy = idx >> 5;
        int xo = xy % 14, yo = xy / 14;
        float acc = bias[c];
#pragma unroll
        for (int i = 0; i < 2; i++) {
            int iy = 4 * yo - 1 + 2 * i;
            if (iy < 0 || iy >= 56) continue;
#pragma unroll
            for (int j = 0; j < 2; j++) {
                int ix = 4 * xo - 1 + 2 * j;
                if (ix < 0 || ix >= 56) continue;
                acc = fmaf(s[(iy * 56 + ix) * 32 + c], w[(i * 2 + j) * 32 + c], acc);
            }
        }
        d[idx] = acc;
    }
}

// ---------------- windowed attention (49 tokens, d=32), one CTA per window ----
__global__ __launch_bounds__(256)
void window_attn(int scaleId)
{
    // rows padded to 64 so the lane+32 path never reads outside the array
    __shared__ float sQ[64 * 33];
    __shared__ float sK[64 * 33];
    __shared__ float sV[64 * 33];

    const float *Qb, *Kb, *Vb;
    int side, nside, headOff, ntile, seq;
    if (scaleId == 0)      { Qb = g_Q;  Kb = g_K;  Vb = g_V;  side = 56; nside = 8; headOff = 0; ntile = 1;  seq = 3136; }
    else if (scaleId == 1) { Qb = g_Q1; Kb = g_K1; Vb = g_V1; side = 28; nside = 4; headOff = 4; ntile = 4;  seq = 784;  }
    else                   { Qb = g_Q2; Kb = g_K2; Vb = g_V2; side = 14; nside = 2; headOff = 8; ntile = 16; seq = 196;  }

    const int nwin = nside * nside;
    const int rg = blockIdx.x % nwin;
    const int hl = (blockIdx.x / nwin) & 3;
    const int b  = blockIdx.x / (nwin * 4);
    const int hb = rg / nside, wb = rg % nside;

    const int imgIdx = (scaleId == 0) ? (b * 12 + hl) : (b * 4 + hl);
    const float* Qp = Qb + (size_t)imgIdx * seq * 32;
    const float* Kp = Kb + (size_t)imgIdx * seq * 32;
    const float* Vp = Vb + (size_t)imgIdx * seq * 32;

    for (int idx = threadIdx.x; idx < 49 * 32; idx += 256) {
        int p = idx >> 5, k = idx & 31;
        int yy = hb * 7 + p / 7, xx = wb * 7 + p % 7;
        int off = (yy * side + xx) * 32 + k;
        sQ[p * 33 + k] = Qp[off];
        sK[p * 33 + k] = Kp[off];
        sV[p * 33 + k] = Vp[off];
    }
    __syncthreads();

    const int lane = threadIdx.x & 31;
    const int warp = threadIdx.x >> 5;
    const float scale = 0.17677669529663687f;   // 32^-0.5
    const bool hi = (lane < 17);                // lane covers q = lane and q = lane+32

    for (int p = warp; p < 49; p += 8) {
        float s0 = 0.f, s1 = 0.f;
#pragma unroll 8
        for (int k = 0; k < 32; k++) {
            float qv = sQ[p * 33 + k];
            s0 = fmaf(qv, sK[lane * 33 + k], s0);
            s1 = fmaf(qv, sK[(lane + 32) * 33 + k], s1);  // padded rows: unused lanes masked below
        }
        float t0 = s0 * scale;
        float t1 = s1 * scale;
        float m = hi ? fmaxf(t0, t1) : t0;
#pragma unroll
        for (int o = 16; o > 0; o >>= 1) m = fmaxf(m, __shfl_xor_sync(0xffffffffu, m, o));
        float e0 = __expf(t0 - m);
        float e1 = hi ? __expf(t1 - m) : 0.f;
        float sum = e0 + e1;
#pragma unroll
        for (int o = 16; o > 0; o >>= 1) sum += __shfl_xor_sync(0xffffffffu, sum, o);
        float rinv = 1.f / sum;

        float acc = 0.f;
#pragma unroll
        for (int q = 0; q < 49; q++) {
            float pq = (q < 32) ? __shfl_sync(0xffffffffu, e0, q)
                                : __shfl_sync(0xffffffffu, e1, q - 32);
            acc = fmaf(pq, sV[q * 33 + lane], acc);
        }
        acc *= rinv;

        int col = (headOff + hl) * 32 + lane;
        for (int t = 0; t < ntile; t++) {
            int nout = (t * nwin + rg) * 49 + p;   // patch-order token index
            g_Z[((size_t)b * NTOK + nout) * 384 + col] = acc;
        }
    }
}

// ---------------- launch ------------------------------------------------------
extern "C" void kernel_launch(void* const* d_in, const int* in_sizes, int n_in,
                              void* d_out, int out_size)
{
    const float* x     = (const float*)d_in[0];
    const float* Wq    = (const float*)d_in[1];
    const float* Wkv   = (const float*)d_in[2];
    const float* Wproj = (const float*)d_in[3];
    const float* bproj = (const float*)d_in[4];
    const float* c1w   = (const float*)d_in[5];
    const float* c1b   = (const float*)d_in[6];
    const float* c2w   = (const float*)d_in[7];
    const float* c2b   = (const float*)d_in[8];
    float* out = (float*)d_out;

    gemm_qkv<<<dim3(9, 784), 256>>>(x, Wq, Wkv);
    dwconv1<<<dim3(128, 3), 256>>>(c1w, c1b);
    dwconv2<<<dim3(128, 3), 256>>>(c2w, c2b);
    window_attn<<<32 * 4 * 64, 256>>>(0);
    window_attn<<<32 * 4 * 16, 256>>>(1);
    window_attn<<<32 * 4 * 4,  256>>>(2);
    gemm_proj<<<dim3(3, 784), 256>>>(Wproj, bproj, out);
}

// round 3
// speedup vs baseline: 2.1804x; 2.1804x over previous
#include <cuda_runtime.h>
#include <cuda_bf16.h>
#include <cstdint>

#define B_    32
#define NTOK  3136
#define NH    12
#define D_    32

// ---------------- scratch (device globals; no allocation allowed) -------------
__device__ __align__(16) float g_Q[(size_t)B_ * NH * NTOK * D_];   // [b*12+h][n][d]
__device__ __align__(16) float g_K[(size_t)B_ * NH * NTOK * D_];
__device__ __align__(16) float g_V[(size_t)B_ * NH * NTOK * D_];
__device__ __align__(16) float g_Q1[B_ * 4 * 784 * D_];
__device__ __align__(16) float g_K1[B_ * 4 * 784 * D_];
__device__ __align__(16) float g_V1[B_ * 4 * 784 * D_];
__device__ __align__(16) float g_Q2[B_ * 4 * 196 * D_];
__device__ __align__(16) float g_K2[B_ * 4 * 196 * D_];
__device__ __align__(16) float g_V2[B_ * 4 * 196 * D_];

#define XELEMS ((size_t)B_ * NTOK * 384)
__device__ __align__(16) __nv_bfloat16 g_Xh[XELEMS];
__device__ __align__(16) __nv_bfloat16 g_Xl[XELEMS];
__device__ __align__(16) __nv_bfloat16 g_Zh[XELEMS];
__device__ __align__(16) __nv_bfloat16 g_Zl[XELEMS];
// transposed weights, [n][k]: rows 0..1151 = qkv output cols, 1152..1535 = proj cols
__device__ __align__(16) __nv_bfloat16 g_WTh[1536 * 384];
__device__ __align__(16) __nv_bfloat16 g_WTl[1536 * 384];

// ---------------- helpers -------------------------------------------------------
__device__ __forceinline__ uint32_t smem_u32(const void* p) {
    uint32_t a;
    asm("{ .reg .u64 t; cvta.to.shared.u64 t, %1; cvt.u32.u64 %0, t; }" : "=r"(a) : "l"(p));
    return a;
}
__device__ __forceinline__ void cp16(uint32_t dst, const void* src) {
    asm volatile("cp.async.cg.shared.global [%0], [%1], 16;" :: "r"(dst), "l"(src));
}
__device__ __forceinline__ void ldm_x4(uint32_t* r, uint32_t a) {
    asm volatile("ldmatrix.sync.aligned.m8n8.x4.shared.b16 {%0,%1,%2,%3}, [%4];"
                 : "=r"(r[0]), "=r"(r[1]), "=r"(r[2]), "=r"(r[3]) : "r"(a));
}
__device__ __forceinline__ void mma16816(float* d, const uint32_t* a, const uint32_t* b) {
    asm volatile(
        "mma.sync.aligned.m16n8k16.row.col.f32.bf16.bf16.f32 "
        "{%0,%1,%2,%3}, {%4,%5,%6,%7}, {%8,%9}, {%0,%1,%2,%3};"
        : "+f"(d[0]), "+f"(d[1]), "+f"(d[2]), "+f"(d[3])
        : "r"(a[0]), "r"(a[1]), "r"(a[2]), "r"(a[3]), "r"(b[0]), "r"(b[1]));
}

// ---------------- split / transpose kernels ------------------------------------
__global__ void split_x(const float4* __restrict__ src) {
    uint2* hiP = (uint2*)g_Xh;
    uint2* loP = (uint2*)g_Xl;
    const int n4 = (int)(XELEMS / 4);
    const int stride = gridDim.x * blockDim.x;
    for (int i = blockIdx.x * blockDim.x + threadIdx.x; i < n4; i += stride) {
        float4 f = src[i];
        uint32_t x = __float_as_uint(f.x), y = __float_as_uint(f.y);
        uint32_t z = __float_as_uint(f.z), w = __float_as_uint(f.w);
        uint2 h;
        h.x = __byte_perm(x, y, 0x7632);
        h.y = __byte_perm(z, w, 0x7632);
        float l0 = f.x - __uint_as_float(x & 0xFFFF0000u);
        float l1 = f.y - __uint_as_float(y & 0xFFFF0000u);
        float l2 = f.z - __uint_as_float(z & 0xFFFF0000u);
        float l3 = f.w - __uint_as_float(w & 0xFFFF0000u);
        uint2 l;
        asm("cvt.rn.bf16x2.f32 %0, %1, %2;" : "=r"(l.x) : "f"(l1), "f"(l0));
        asm("cvt.rn.bf16x2.f32 %0, %1, %2;" : "=r"(l.y) : "f"(l3), "f"(l2));
        hiP[i] = h;
        loP[i] = l;
    }
}

__global__ void make_wt(const float* __restrict__ Wq, const float* __restrict__ Wkv,
                        const float* __restrict__ Wproj) {
    int idx = blockIdx.x * 256 + threadIdx.x;
    if (idx >= 1536 * 384) return;
    int nrow = idx / 384, k = idx % 384;
    float v;
    if (nrow < 384)       v = Wq[(size_t)k * 384 + nrow];
    else if (nrow < 1152) v = Wkv[(size_t)k * 768 + (nrow - 384)];
    else                  v = Wproj[(size_t)k * 384 + (nrow - 1152)];
    uint32_t bits = __float_as_uint(v);
    float hf = __uint_as_float(bits & 0xFFFF0000u);
    g_WTh[idx] = __ushort_as_bfloat16((unsigned short)(bits >> 16));
    g_WTl[idx] = __float2bfloat16(v - hf);
}

// ---------------- HMMA GEMM: 128x128 CTA tile, K=384, 3-term bf16 split ---------
// smem tile: 128 rows x 32 bf16, row stride 40 bf16 (80B) -> conflict-free ldmatrix
#define TSROW 40
#define TILEB (128 * TSROW * 2)      // 10240
#define STAGEB (4 * TILEB)           // Ah, Al, Bh, Bl = 40960
#define SMEM_GEMM (2 * STAGEB)       // 81920

__global__ __launch_bounds__(256)
void gemm_mma(const float* __restrict__ bias, float* __restrict__ out, int mode)
{
    extern __shared__ __align__(16) char smem[];
    const uint32_t sb = smem_u32(smem);
    const int tid = threadIdx.x, lane = tid & 31, wid = tid >> 5;
    const int warpM = wid & 1, warpN = wid >> 1;    // 2 x 4 warp grid
    const int rowBase = blockIdx.y * 128, colBase = blockIdx.x * 128;

    const __nv_bfloat16* Ahg = (mode == 0 ? g_Xh : g_Zh) + (size_t)rowBase * 384;
    const __nv_bfloat16* Alg = (mode == 0 ? g_Xl : g_Zl) + (size_t)rowBase * 384;
    const int brow = (mode == 0 ? 0 : 1152) + colBase;
    const __nv_bfloat16* Bhg = g_WTh + (size_t)brow * 384;
    const __nv_bfloat16* Blg = g_WTl + (size_t)brow * 384;

    // per-thread load coords (2 segments per tile per thread)
    const int r0 = tid >> 2, s0 = tid & 3;          // segs 0..255
    const int r1 = (tid + 256) >> 2, s1 = tid & 3;  // segs 256..511

    float acc[4][4][4];
#pragma unroll
    for (int i = 0; i < 4; i++)
#pragma unroll
        for (int j = 0; j < 4; j++)
#pragma unroll
            for (int q = 0; q < 4; q++) acc[i][j][q] = 0.f;

    auto load_chunk = [&](int c, int stg) {
        const uint32_t base = sb + stg * STAGEB;
        const int k0 = c * 32;
        {
            uint32_t so = base + (uint32_t)(r0 * (TSROW * 2) + s0 * 16);
            size_t go = (size_t)r0 * 384 + k0 + s0 * 8;
            cp16(so,             Ahg + go);
            cp16(so + TILEB,     Alg + go);
            cp16(so + 2 * TILEB, Bhg + go);
            cp16(so + 3 * TILEB, Blg + go);
        }
        {
            uint32_t so = base + (uint32_t)(r1 * (TSROW * 2) + s1 * 16);
            size_t go = (size_t)r1 * 384 + k0 + s1 * 8;
            cp16(so,             Ahg + go);
            cp16(so + TILEB,     Alg + go);
            cp16(so + 2 * TILEB, Bhg + go);
            cp16(so + 3 * TILEB, Blg + go);
        }
        asm volatile("cp.async.commit_group;" ::: "memory");
    };

    // ldmatrix per-lane addressing
    const int rA = lane & 15, cA = (lane >> 4) << 3;            // A tiles
    const int rB = (lane & 7) + ((lane & 16) ? 8 : 0);          // B tiles (2 n-tiles/x4)
    const int cB = ((lane >> 3) & 1) << 3;

    load_chunk(0, 0);

    for (int c = 0; c < 12; c++) {
        if (c < 11) load_chunk(c + 1, (c + 1) & 1);
        if (c < 11) asm volatile("cp.async.wait_group 1;" ::: "memory");
        else        asm volatile("cp.async.wait_group 0;" ::: "memory");
        __syncthreads();

        const uint32_t base = sb + (c & 1) * STAGEB;
#pragma unroll
        for (int kk = 0; kk < 32; kk += 16) {
            uint32_t ah[4][4], al[4][4], bx[4][2];
#pragma unroll
            for (int i = 0; i < 4; i++) {
                uint32_t addr = base +
                    (uint32_t)((warpM * 64 + i * 16 + rA) * (TSROW * 2) + (kk + cA) * 2);
                ldm_x4(ah[i], addr);
                ldm_x4(al[i], addr + TILEB);
            }
            // Bh
#pragma unroll
            for (int jj = 0; jj < 2; jj++) {
                uint32_t rr[4];
                uint32_t addr = base + 2 * TILEB +
                    (uint32_t)((warpN * 32 + jj * 16 + rB) * (TSROW * 2) + (kk + cB) * 2);
                ldm_x4(rr, addr);
                bx[2 * jj][0] = rr[0]; bx[2 * jj][1] = rr[1];
                bx[2 * jj + 1][0] = rr[2]; bx[2 * jj + 1][1] = rr[3];
            }
#pragma unroll
            for (int i = 0; i < 4; i++)
#pragma unroll
                for (int j = 0; j < 4; j++) mma16816(acc[i][j], ah[i], bx[j]);
#pragma unroll
            for (int i = 0; i < 4; i++)
#pragma unroll
                for (int j = 0; j < 4; j++) mma16816(acc[i][j], al[i], bx[j]);
            // Bl (reuse bx)
#pragma unroll
            for (int jj = 0; jj < 2; jj++) {
                uint32_t rr[4];
                uint32_t addr = base + 3 * TILEB +
                    (uint32_t)((warpN * 32 + jj * 16 + rB) * (TSROW * 2) + (kk + cB) * 2);
                ldm_x4(rr, addr);
                bx[2 * jj][0] = rr[0]; bx[2 * jj][1] = rr[1];
                bx[2 * jj + 1][0] = rr[2]; bx[2 * jj + 1][1] = rr[3];
            }
#pragma unroll
            for (int i = 0; i < 4; i++)
#pragma unroll
                for (int j = 0; j < 4; j++) mma16816(acc[i][j], ah[i], bx[j]);
        }
        __syncthreads();
    }

    // ---------------- epilogue ----------------
#pragma unroll
    for (int j = 0; j < 4; j++) {
        const int cg = colBase + warpN * 32 + j * 8 + 2 * (lane & 3);
#pragma unroll
        for (int i = 0; i < 4; i++) {
            const int m = rowBase + warpM * 64 + i * 16 + (lane >> 2);
            if (mode == 0) {
                int bb = m / NTOK, n = m % NTOK;
                float* dst;
                int d;
                if (cg < 384) {
                    dst = g_Q + (((size_t)bb * 12 + (cg >> 5)) * NTOK + n) * 32;
                    d = cg & 31;
                } else {
                    int j2 = cg - 384;
                    float* basep = (j2 >= 384) ? g_V : g_K;
                    dst = basep + (((size_t)bb * 12 + ((j2 >> 5) % 12)) * NTOK + n) * 32;
                    d = j2 & 31;
                }
                *(float2*)(dst + d)            = make_float2(acc[i][j][0], acc[i][j][1]);
                *(float2*)(dst + d + 8 * 32)   = make_float2(acc[i][j][2], acc[i][j][3]);
            } else {
                float b0 = bias[cg], b1 = bias[cg + 1];
                *(float2*)(out + (size_t)m * 384 + cg) =
                    make_float2(acc[i][j][0] + b0, acc[i][j][1] + b1);
                *(float2*)(out + (size_t)(m + 8) * 384 + cg) =
                    make_float2(acc[i][j][2] + b0, acc[i][j][3] + b1);
            }
        }
    }
}

// ---------------- depthwise convs -----------------------------------------------
__global__ void dwconv1(const float* __restrict__ w, const float* __restrict__ bias)
{
    int which = blockIdx.y;
    const float* src = which == 0 ? g_Q : which == 1 ? g_K : g_V;
    float* dst       = which == 0 ? g_Q1 : which == 1 ? g_K1 : g_V1;
    int bg = blockIdx.x;
    int b = bg >> 2, hl = bg & 3;
    const float* s = src + ((size_t)(b * 12 + 4 + hl)) * NTOK * 32;
    float* d = dst + (size_t)bg * 784 * 32;
    for (int idx = threadIdx.x; idx < 784 * 32; idx += blockDim.x) {
        int c = idx & 31;
        int xy = idx >> 5;
        int xo = xy % 28, yo = xy / 28;
        float acc = bias[c];
#pragma unroll
        for (int i = 0; i < 2; i++)
#pragma unroll
            for (int j = 0; j < 2; j++)
                acc = fmaf(s[((2 * yo + i) * 56 + 2 * xo + j) * 32 + c],
                           w[(i * 2 + j) * 32 + c], acc);
        d[idx] = acc;
    }
}

__global__ void dwconv2(const float* __restrict__ w, const float* __restrict__ bias)
{
    int which = blockIdx.y;
    const float* src = which == 0 ? g_Q : which == 1 ? g_K : g_V;
    float* dst       = which == 0 ? g_Q2 : which == 1 ? g_K2 : g_V2;
    int bg = blockIdx.x;
    int b = bg >> 2, hl = bg & 3;
    const float* s = src + ((size_t)(b * 12 + 8 + hl)) * NTOK * 32;
    float* d = dst + (size_t)bg * 196 * 32;
    for (int idx = threadIdx.x; idx < 196 * 32; idx += blockDim.x) {
        int c = idx & 31;
        int xy = idx >> 5;
        int xo = xy % 14, yo = xy / 14;
        float acc = bias[c];
#pragma unroll
        for (int i = 0; i < 2; i++) {
            int iy = 4 * yo - 1 + 2 * i;
            if (iy < 0 || iy >= 56) continue;
#pragma unroll
            for (int j = 0; j < 2; j++) {
                int ix = 4 * xo - 1 + 2 * j;
                if (ix < 0 || ix >= 56) continue;
                acc = fmaf(s[(iy * 56 + ix) * 32 + c], w[(i * 2 + j) * 32 + c], acc);
            }
        }
        d[idx] = acc;
    }
}

// ---------------- windowed attention; writes Z as bf16 hi/lo --------------------
__global__ __launch_bounds__(256)
void window_attn(int scaleId)
{
    __shared__ float sQ[64 * 33];
    __shared__ float sK[64 * 33];
    __shared__ float sV[64 * 33];

    const float *Qb, *Kb, *Vb;
    int side, nside, headOff, ntile, seq;
    if (scaleId == 0)      { Qb = g_Q;  Kb = g_K;  Vb = g_V;  side = 56; nside = 8; headOff = 0; ntile = 1;  seq = 3136; }
    else if (scaleId == 1) { Qb = g_Q1; Kb = g_K1; Vb = g_V1; side = 28; nside = 4; headOff = 4; ntile = 4;  seq = 784;  }
    else                   { Qb = g_Q2; Kb = g_K2; Vb = g_V2; side = 14; nside = 2; headOff = 8; ntile = 16; seq = 196;  }

    const int nwin = nside * nside;
    const int rg = blockIdx.x % nwin;
    const int hl = (blockIdx.x / nwin) & 3;
    const int b  = blockIdx.x / (nwin * 4);
    const int hb = rg / nside, wb = rg % nside;

    const int imgIdx = (scaleId == 0) ? (b * 12 + hl) : (b * 4 + hl);
    const float* Qp = Qb + (size_t)imgIdx * seq * 32;
    const float* Kp = Kb + (size_t)imgIdx * seq * 32;
    const float* Vp = Vb + (size_t)imgIdx * seq * 32;

    for (int idx = threadIdx.x; idx < 49 * 32; idx += 256) {
        int p = idx >> 5, k = idx & 31;
        int yy = hb * 7 + p / 7, xx = wb * 7 + p % 7;
        int off = (yy * side + xx) * 32 + k;
        sQ[p * 33 + k] = Qp[off];
        sK[p * 33 + k] = Kp[off];
        sV[p * 33 + k] = Vp[off];
    }
    __syncthreads();

    const int lane = threadIdx.x & 31;
    const int warp = threadIdx.x >> 5;
    const float scale = 0.17677669529663687f;
    const bool hi = (lane < 17);

    for (int p = warp; p < 49; p += 8) {
        float s0 = 0.f, s1 = 0.f;
#pragma unroll 8
        for (int k = 0; k < 32; k++) {
            float qv = sQ[p * 33 + k];
            s0 = fmaf(qv, sK[lane * 33 + k], s0);
            s1 = fmaf(qv, sK[(lane + 32) * 33 + k], s1);
        }
        float t0 = s0 * scale;
        float t1 = s1 * scale;
        float m = hi ? fmaxf(t0, t1) : t0;
#pragma unroll
        for (int o = 16; o > 0; o >>= 1) m = fmaxf(m, __shfl_xor_sync(0xffffffffu, m, o));
        float e0 = __expf(t0 - m);
        float e1 = hi ? __expf(t1 - m) : 0.f;
        float sum = e0 + e1;
#pragma unroll
        for (int o = 16; o > 0; o >>= 1) sum += __shfl_xor_sync(0xffffffffu, sum, o);
        float rinv = 1.f / sum;

        float acc = 0.f;
#pragma unroll
        for (int q = 0; q < 49; q++) {
            float pq = (q < 32) ? __shfl_sync(0xffffffffu, e0, q)
                                : __shfl_sync(0xffffffffu, e1, q - 32);
            acc = fmaf(pq, sV[q * 33 + lane], acc);
        }
        acc *= rinv;

        __nv_bfloat16 h = __float2bfloat16(acc);
        __nv_bfloat16 l = __float2bfloat16(acc - __bfloat162float(h));
        int col = (headOff + hl) * 32 + lane;
        for (int t = 0; t < ntile; t++) {
            int nout = (t * nwin + rg) * 49 + p;
            size_t off = ((size_t)b * NTOK + nout) * 384 + col;
            g_Zh[off] = h;
            g_Zl[off] = l;
        }
    }
}

// ---------------- launch ---------------------------------------------------------
extern "C" void kernel_launch(void* const* d_in, const int* in_sizes, int n_in,
                              void* d_out, int out_size)
{
    const float* x     = (const float*)d_in[0];
    const float* Wq    = (const float*)d_in[1];
    const float* Wkv   = (const float*)d_in[2];
    const float* Wproj = (const float*)d_in[3];
    const float* bproj = (const float*)d_in[4];
    const float* c1w   = (const float*)d_in[5];
    const float* c1b   = (const float*)d_in[6];
    const float* c2w   = (const float*)d_in[7];
    const float* c2b   = (const float*)d_in[8];
    float* out = (float*)d_out;

    cudaFuncSetAttribute(gemm_mma, cudaFuncAttributeMaxDynamicSharedMemorySize, SMEM_GEMM);

    split_x<<<4704, 256>>>((const float4*)x);
    make_wt<<<2304, 256>>>(Wq, Wkv, Wproj);
    gemm_mma<<<dim3(9, 784), 256, SMEM_GEMM>>>(nullptr, nullptr, 0);
    dwconv1<<<dim3(128, 3), 256>>>(c1w, c1b);
    dwconv2<<<dim3(128, 3), 256>>>(c2w, c2b);
    window_attn<<<32 * 4 * 64, 256>>>(0);
    window_attn<<<32 * 4 * 16, 256>>>(1);
    window_attn<<<32 * 4 * 4,  256>>>(2);
    gemm_mma<<<dim3(3, 784), 256, SMEM_GEMM>>>(bproj, out, 1);
}